// round 13
// baseline (speedup 1.0000x reference)
#include <cuda_runtime.h>
#include <math.h>
#include <stdint.h>

// ---------------- problem constants ----------------
#define BSZ    2
#define LSEQ   4096
#define DMODEL 1024
#define DIEXP  2048
#define NH     32
#define HP     64
#define DS     128
#define CS     64
#define NC     64
#define DPROJ  4384
#define CONVD  2304
#define ROWS   8192
#define NBCH   (BSZ * NC * NH)          // 4096

// ---------------- device scratch ----------------
__device__ float g_zxbcdt[(size_t)ROWS * DPROJ];
__device__ float g_xt    [(size_t)NBCH * HP * CS];        // (x*dt)^T tf32-rounded: [p][s]
__device__ float g_bc    [(size_t)ROWS * 256];            // [row][B(128)|C(128)], tf32
__device__ float g_bt    [(size_t)BSZ * NC * DS * CS];    // B^T per (b,c): [n][s], tf32
__device__ float g_acum  [NBCH * CS];
__device__ float g_dt    [ROWS * NH];
__device__ float g_adt   [ROWS * NH];
__device__ float g_CB    [BSZ * NC * CS * CS];
__device__ float g_states[(size_t)NBCH * HP * DS];        // head reused as rounded-u scratch
__device__ float g_dchunk[NBCH];
__device__ float g_y     [(size_t)ROWS * DIEXP];
__device__ float g_WT    [(size_t)DPROJ * DMODEL + (size_t)DMODEL * DIEXP];

// ---------------- helpers ----------------
__device__ __forceinline__ uint32_t f2tf32(float x) {
    uint32_t r;
    asm("cvt.rna.tf32.f32 %0, %1;" : "=r"(r) : "f"(x));
    return r;
}
__device__ __forceinline__ float tf32r(float x) { return __uint_as_float(f2tf32(x)); }

__device__ __forceinline__ uint32_t smem_u32(const void* p) {
    uint32_t a;
    asm("{ .reg .u64 t; cvta.to.shared.u64 t, %1; cvt.u32.u64 %0, t; }" : "=r"(a) : "l"(p));
    return a;
}
__device__ __forceinline__ void cp_async16(uint32_t dst, const void* src) {
    asm volatile("cp.async.cg.shared.global [%0], [%1], 16;" :: "r"(dst), "l"(src) : "memory");
}
#define MMA_TF32(acc, af, bf)                                               \
    asm volatile(                                                           \
        "mma.sync.aligned.m16n8k8.row.col.f32.tf32.tf32.f32 "               \
        "{%0,%1,%2,%3}, {%4,%5,%6,%7}, {%8,%9}, {%0,%1,%2,%3};\n"           \
        : "+f"((acc)[0]), "+f"((acc)[1]), "+f"((acc)[2]), "+f"((acc)[3])    \
        : "r"((af)[0]), "r"((af)[1]), "r"((af)[2]), "r"((af)[3]),           \
          "r"((bf)[0]), "r"((bf)[1]))

// =====================================================================
// tf32 mma.sync dense GEMM — EXACT R8 proven version (do not touch)
// =====================================================================
#define GSTG 3
#define ROWB 144
#define STG_BYTES (128 * ROWB)

__global__ __launch_bounds__(256) void gemm_mma_kernel(
    const float* __restrict__ A, const float* __restrict__ BT,
    float* __restrict__ C, int M, int N, int K)
{
    extern __shared__ char sm[];
    const uint32_t sb = smem_u32(sm);
    const int tid  = threadIdx.x;
    const int wid  = tid >> 5, lane = tid & 31;
    const int gid  = lane >> 2, tig = lane & 3;
    const int wm   = wid >> 1,  wn  = wid & 1;
    const int mBase = blockIdx.y * 128, nBase = blockIdx.x * 128;

    float acc[2][8][4];
    #pragma unroll
    for (int t = 0; t < 2; ++t)
        #pragma unroll
        for (int j = 0; j < 8; ++j)
            #pragma unroll
            for (int e = 0; e < 4; ++e) acc[t][j][e] = 0.f;

    const int KT = K >> 5;
    const int lrow = tid >> 3, lc16 = tid & 7;
    const int aOff = (wm * 32 + gid) * ROWB + tig * 4;
    const int bOff = (wn * 64 + gid) * ROWB + tig * 4;

    auto load_stage = [&](int kt, int s) {
        const int k0 = kt << 5;
        const uint32_t ab = sb + s * STG_BYTES;
        const uint32_t bb = sb + GSTG * STG_BYTES + s * STG_BYTES;
        #pragma unroll
        for (int i = 0; i < 4; ++i) {
            int row = lrow + i * 32;
            cp_async16(ab + row * ROWB + lc16 * 16,
                       A + (size_t)(mBase + row) * K + k0 + lc16 * 4);
        }
        #pragma unroll
        for (int i = 0; i < 4; ++i) {
            int row = lrow + i * 32;
            int nr = nBase + row; if (nr >= N) nr = N - 1;
            cp_async16(bb + row * ROWB + lc16 * 16,
                       BT + (size_t)nr * K + k0 + lc16 * 4);
        }
        asm volatile("cp.async.commit_group;" ::: "memory");
    };

    load_stage(0, 0);
    if (KT > 1) load_stage(1, 1);

    for (int kt = 0; kt < KT; ++kt) {
        const int s = kt % GSTG;
        asm volatile("cp.async.wait_group 1;" ::: "memory");
        __syncthreads();

        const char* As = sm + s * STG_BYTES + aOff;
        const char* Bs = sm + GSTG * STG_BYTES + s * STG_BYTES + bOff;

        #pragma unroll
        for (int ks = 0; ks < 4; ++ks) {
            const int kb = ks * 32;
            uint32_t af[2][4];
            #pragma unroll
            for (int t = 0; t < 2; ++t) {
                const char* a = As + t * (16 * ROWB) + kb;
                af[t][0] = *(const uint32_t*)(a);
                af[t][1] = *(const uint32_t*)(a + 8 * ROWB);
                af[t][2] = *(const uint32_t*)(a + 16);
                af[t][3] = *(const uint32_t*)(a + 8 * ROWB + 16);
            }
            uint32_t bf[8][2];
            #pragma unroll
            for (int j = 0; j < 8; ++j) {
                const char* bp = Bs + j * (8 * ROWB) + kb;
                bf[j][0] = *(const uint32_t*)(bp);
                bf[j][1] = *(const uint32_t*)(bp + 16);
            }
            #pragma unroll
            for (int t = 0; t < 2; ++t)
                #pragma unroll
                for (int j = 0; j < 8; ++j)
                    MMA_TF32(acc[t][j], af[t], bf[j]);
        }
        if (kt + 2 < KT) load_stage(kt + 2, (kt + 2) % GSTG);
    }

    #pragma unroll
    for (int t = 0; t < 2; ++t) {
        int r0 = mBase + wm * 32 + t * 16 + gid;
        #pragma unroll
        for (int j = 0; j < 8; ++j) {
            int c0 = nBase + wn * 64 + j * 8 + tig * 2;
            if (c0 + 1 < N) {
                *(float2*)&C[(size_t)r0 * N + c0]       = make_float2(acc[t][j][0], acc[t][j][1]);
                *(float2*)&C[(size_t)(r0 + 8) * N + c0] = make_float2(acc[t][j][2], acc[t][j][3]);
            } else if (c0 < N) {
                C[(size_t)r0 * N + c0]       = acc[t][j][0];
                C[(size_t)(r0 + 8) * N + c0] = acc[t][j][2];
            }
        }
    }
}

// ---------------- pre-rounding / weight transpose ----------------
__global__ __launch_bounds__(256) void round_u_kernel(const float* __restrict__ u, float* __restrict__ o)
{
    int idx = blockIdx.x * 256 + threadIdx.x;
    if (idx < ROWS * DMODEL / 4) {
        float4 v = ((const float4*)u)[idx];
        v.x = tf32r(v.x); v.y = tf32r(v.y); v.z = tf32r(v.z); v.w = tf32r(v.w);
        ((float4*)o)[idx] = v;
    }
}

__global__ __launch_bounds__(256) void transpose_round_kernel(
    const float* __restrict__ W, float* __restrict__ WT, int K, int N)
{
    __shared__ float tile[32][33];
    const int bx = blockIdx.x * 32, by = blockIdx.y * 32;
    const int x = threadIdx.x & 31, y = threadIdx.x >> 5;
    #pragma unroll
    for (int i = 0; i < 32; i += 8) {
        int k = by + y + i, n = bx + x;
        tile[y + i][x] = (k < K && n < N) ? W[(size_t)k * N + n] : 0.f;
    }
    __syncthreads();
    #pragma unroll
    for (int i = 0; i < 32; i += 8) {
        int n = bx + y + i, k = by + x;
        if (n < N && k < K) WT[(size_t)n * K + k] = tf32r(tile[x][y + i]);
    }
}

// ---------------- dt / A*dt (before conv; conv folds dt into x) ----
__global__ __launch_bounds__(256) void dt_kernel(
    const float* __restrict__ dt_bias, const float* __restrict__ A_log)
{
    int idx = blockIdx.x * 256 + threadIdx.x;
    if (idx >= ROWS * NH) return;
    int r = idx >> 5;
    int h = idx & 31;
    float x = g_zxbcdt[(size_t)r * DPROJ + (DPROJ - NH) + h] + dt_bias[h];
    float sp = (x > 20.f) ? x : log1pf(expf(x));   // keep precise softplus
    g_dt[idx]  = sp;
    g_adt[idx] = -expf(A_log[h]) * sp;
}

// ---------------- conv + SiLU (fast exp); xt stores tf32r(x*dt) -------------
__global__ __launch_bounds__(256) void conv_silu_kernel(
    const float* __restrict__ conv_w, const float* __restrict__ conv_b)
{
    int idx = blockIdx.x * 256 + threadIdx.x;
    if (idx >= CONVD * (ROWS / 4)) return;
    const int ch = idx % CONVD;
    const int r4 = idx / CONVD;
    const int r0 = r4 * 4;
    const int b  = r0 >> 12;
    const int l0 = r0 & (LSEQ - 1);

    const float w0 = conv_w[ch * 4 + 0], w1 = conv_w[ch * 4 + 1];
    const float w2 = conv_w[ch * 4 + 2], w3 = conv_w[ch * 4 + 3];
    const float bias = conv_b[ch];

    float in[7];
    #pragma unroll
    for (int i = 0; i < 7; ++i) {
        int l = l0 - 3 + i;
        in[i] = (l >= 0) ? g_zxbcdt[(size_t)(r0 - 3 + i) * DPROJ + DIEXP + ch] : 0.f;
    }
    float o[4];
    #pragma unroll
    for (int k = 0; k < 4; ++k) {
        float a = bias;
        a = fmaf(in[k],     w0, a);
        a = fmaf(in[k + 1], w1, a);
        a = fmaf(in[k + 2], w2, a);
        a = fmaf(in[k + 3], w3, a);
        o[k] = a / (1.f + __expf(-a));
    }

    const int c  = l0 >> 6;
    const int s0 = l0 & 63;

    if (ch < DIEXP) {
        const int h = ch >> 6, p = ch & 63;
        #pragma unroll
        for (int k = 0; k < 4; ++k)
            o[k] = tf32r(o[k] * g_dt[(r0 + k) * NH + h]);
        const size_t base = (((size_t)((b * NC + c) * NH + h)) * HP + p) * CS + s0;
        *(float4*)&g_xt[base] = make_float4(o[0], o[1], o[2], o[3]);
    } else {
        const int cc = ch - DIEXP;   // 0..255
        #pragma unroll
        for (int k = 0; k < 4; ++k)
            g_bc[(size_t)(r0 + k) * 256 + cc] = tf32r(o[k]);
        if (cc < DS) {
            const size_t base = ((size_t)(b * NC + c) * DS + cc) * CS + s0;
            *(float4*)&g_bt[base] = make_float4(tf32r(o[0]), tf32r(o[1]), tf32r(o[2]), tf32r(o[3]));
        }
    }
}

// ---------------- per-(b,c,h) cumsum of adt ----------------
__global__ __launch_bounds__(256) void acum_kernel()
{
    int bch = blockIdx.x * 256 + threadIdx.x;
    if (bch >= NBCH) return;
    int h = bch & 31;
    int c = (bch >> 5) & 63;
    int b = bch >> 11;
    int rowBase = b * LSEQ + c * CS;
    float a = 0.f;
    #pragma unroll 8
    for (int s = 0; s < CS; ++s) {
        a += g_adt[(rowBase + s) * NH + h];
        g_acum[bch * CS + s] = a;
    }
    g_dchunk[bch] = __expf(a);
}

// ---------------- CB gram via mma ----------------
__global__ __launch_bounds__(256) void cb_kernel()
{
    extern __shared__ float dsm[];
    float* As = dsm;
    float* Bs = dsm + 64 * 132;
    const int bc = blockIdx.x;
    const int rowBase = bc * CS;
    const int tid = threadIdx.x;
    const int wid = tid >> 5, lane = tid & 31;
    const int gid = lane >> 2, tig = lane & 3;
    const int wm = wid >> 2, wn = wid & 3;

    for (int t = tid; t < 2048; t += 256) {
        int i = t >> 5, n4 = (t & 31) * 4;
        *(float4*)&As[i * 132 + n4] = *(const float4*)&g_bc[(size_t)(rowBase + i) * 256 + 128 + n4];
        *(float4*)&Bs[i * 132 + n4] = *(const float4*)&g_bc[(size_t)(rowBase + i) * 256 + n4];
    }
    __syncthreads();

    float acc[2][2][4];
    #pragma unroll
    for (int t = 0; t < 2; ++t)
        #pragma unroll
        for (int j = 0; j < 2; ++j)
            #pragma unroll
            for (int e = 0; e < 4; ++e) acc[t][j][e] = 0.f;

    const float* Aw = As + (wm * 32 + gid) * 132 + tig;
    const float* Bw = Bs + (wn * 16 + gid) * 132 + tig;
    #pragma unroll
    for (int ks = 0; ks < 16; ++ks) {
        const int ko = ks * 8;
        uint32_t af[2][4], bf[2][2];
        #pragma unroll
        for (int t = 0; t < 2; ++t) {
            const float* a = Aw + t * (16 * 132) + ko;
            af[t][0] = __float_as_uint(a[0]);
            af[t][1] = __float_as_uint(a[8 * 132]);
            af[t][2] = __float_as_uint(a[4]);
            af[t][3] = __float_as_uint(a[8 * 132 + 4]);
        }
        #pragma unroll
        for (int j = 0; j < 2; ++j) {
            const float* bp = Bw + j * (8 * 132) + ko;
            bf[j][0] = __float_as_uint(bp[0]);
            bf[j][1] = __float_as_uint(bp[4]);
        }
        #pragma unroll
        for (int t = 0; t < 2; ++t)
            #pragma unroll
            for (int j = 0; j < 2; ++j)
                MMA_TF32(acc[t][j], af[t], bf[j]);
    }

    #pragma unroll
    for (int t = 0; t < 2; ++t) {
        int i0 = wm * 32 + t * 16 + gid;
        #pragma unroll
        for (int j = 0; j < 2; ++j) {
            int j0 = wn * 16 + j * 8 + tig * 2;
            *(float2*)&g_CB[bc * 4096 + i0 * 64 + j0]       = make_float2(acc[t][j][0], acc[t][j][1]);
            *(float2*)&g_CB[bc * 4096 + (i0 + 8) * 64 + j0] = make_float2(acc[t][j][2], acc[t][j][3]);
        }
    }
}

// ---------------- states via mma (xt pre-rounded, incl dt) ----------------
__global__ __launch_bounds__(256) void states_kernel()
{
    extern __shared__ float dsm[];
    float* wv = dsm;
    float* As = dsm + 128;
    float* Bs = As + 64 * 68;
    const int c = blockIdx.x, b = blockIdx.y, h = blockIdx.z;
    const int bch = (b * NC + c) * NH + h;
    const int tid = threadIdx.x;
    const int wid = tid >> 5, lane = tid & 31;
    const int gid = lane >> 2, tig = lane & 3;
    const int wm = wid >> 2, wn = wid & 3;

    if (tid < CS) {
        float aend = g_acum[bch * CS + CS - 1];
        float ac   = g_acum[bch * CS + tid];
        wv[tid] = __expf(aend - ac);
    }
    __syncthreads();

    const float* xt = &g_xt[(size_t)bch * (HP * CS)];
    for (int t = tid; t < 1024; t += 256) {
        int p = t >> 4, s4 = (t & 15) * 4;
        float4 v = *(const float4*)&xt[p * CS + s4];
        v.x = tf32r(v.x * wv[s4 + 0]);
        v.y = tf32r(v.y * wv[s4 + 1]);
        v.z = tf32r(v.z * wv[s4 + 2]);
        v.w = tf32r(v.w * wv[s4 + 3]);
        *(float4*)&As[p * 68 + s4] = v;
    }
    const float* bt = &g_bt[(size_t)(b * NC + c) * (DS * CS)];
    for (int t = tid; t < 2048; t += 256) {
        int n = t >> 4, s4 = (t & 15) * 4;
        *(float4*)&Bs[n * 68 + s4] = *(const float4*)&bt[n * CS + s4];
    }
    __syncthreads();

    float acc[2][4][4];
    #pragma unroll
    for (int t = 0; t < 2; ++t)
        #pragma unroll
        for (int j = 0; j < 4; ++j)
            #pragma unroll
            for (int e = 0; e < 4; ++e) acc[t][j][e] = 0.f;

    const float* Aw = As + (wm * 32 + gid) * 68 + tig;
    const float* Bw = Bs + (wn * 32 + gid) * 68 + tig;
    #pragma unroll
    for (int ks = 0; ks < 8; ++ks) {
        const int ko = ks * 8;
        uint32_t af[2][4], bf[4][2];
        #pragma unroll
        for (int t = 0; t < 2; ++t) {
            const float* a = Aw + t * (16 * 68) + ko;
            af[t][0] = __float_as_uint(a[0]);
            af[t][1] = __float_as_uint(a[8 * 68]);
            af[t][2] = __float_as_uint(a[4]);
            af[t][3] = __float_as_uint(a[8 * 68 + 4]);
        }
        #pragma unroll
        for (int j = 0; j < 4; ++j) {
            const float* bp = Bw + j * (8 * 68) + ko;
            bf[j][0] = __float_as_uint(bp[0]);
            bf[j][1] = __float_as_uint(bp[4]);
        }
        #pragma unroll
        for (int t = 0; t < 2; ++t)
            #pragma unroll
            for (int j = 0; j < 4; ++j)
                MMA_TF32(acc[t][j], af[t], bf[j]);
    }

    float* S = &g_states[(size_t)bch * (HP * DS)];
    #pragma unroll
    for (int t = 0; t < 2; ++t) {
        int p0 = wm * 32 + t * 16 + gid;
        #pragma unroll
        for (int j = 0; j < 4; ++j) {
            int n0 = wn * 32 + j * 8 + tig * 2;
            *(float2*)&S[p0 * DS + n0]       = make_float2(acc[t][j][0], acc[t][j][1]);
            *(float2*)&S[(p0 + 8) * DS + n0] = make_float2(acc[t][j][2], acc[t][j][3]);
        }
    }
}

// ---------------- inter-chunk recurrence (float4; writes tf32-rounded) -------
__global__ __launch_bounds__(256) void recur_kernel()
{
    const int bid = blockIdx.x;          // 0 .. BSZ*NH*8-1
    const int bh  = bid >> 3;            // b*NH + h
    const int eo4 = ((bid & 7) << 8) + threadIdx.x;   // float4 index 0..2047
    const int b = bh >> 5, h = bh & 31;

    float4 S = make_float4(0.f, 0.f, 0.f, 0.f);
    for (int c = 0; c < NC; ++c) {
        int bch = (b * NC + c) * NH + h;
        float d = g_dchunk[bch];
        float4* ptr = (float4*)&g_states[(size_t)bch * (HP * DS)] + eo4;
        float4 t = *ptr;
        // states_in, pre-rounded for y's mma (accumulator S stays fp32)
        *ptr = make_float4(tf32r(S.x), tf32r(S.y), tf32r(S.z), tf32r(S.w));
        S.x = fmaf(d, S.x, t.x);
        S.y = fmaf(d, S.y, t.y);
        S.z = fmaf(d, S.z, t.z);
        S.w = fmaf(d, S.w, t.w);
    }
}

// ---------------- Y via mma: Yoff (K=128) + Yd (K=64) ----------------
// Phase A stages pure copies; eac applied to the accumulator between phases.
__global__ __launch_bounds__(256) void y_kernel()
{
    extern __shared__ float dsm[];
    float* avec = dsm;
    float* eac  = dsm + 64;
    float* As   = dsm + 256;
    float* Bs   = As + 64 * 132;
    const int c = blockIdx.x, b = blockIdx.y, h = blockIdx.z;
    const int bch = (b * NC + c) * NH + h;
    const int rowBase = b * LSEQ + c * CS;
    const int tid = threadIdx.x;
    const int wid = tid >> 5, lane = tid & 31;
    const int gid = lane >> 2, tig = lane & 3;
    const int wm = wid >> 2, wn = wid & 3;

    if (tid < CS) {
        float ac = g_acum[bch * CS + tid];
        avec[tid] = ac;
        eac[tid]  = __expf(ac);
    }
    __syncthreads();

    const float* Sin = &g_states[(size_t)bch * (HP * DS)];
    for (int t = tid; t < 2048; t += 256) {
        int i = t >> 5, n4 = (t & 31) * 4;
        *(float4*)&As[i * 132 + n4] = *(const float4*)&g_bc[(size_t)(rowBase + i) * 256 + 128 + n4];
        *(float4*)&Bs[i * 132 + n4] = *(const float4*)&Sin[i * DS + n4];
    }
    __syncthreads();

    float acc[2][2][4];
    #pragma unroll
    for (int t = 0; t < 2; ++t)
        #pragma unroll
        for (int j = 0; j < 2; ++j)
            #pragma unroll
            for (int e = 0; e < 4; ++e) acc[t][j][e] = 0.f;

    {
        const float* Aw = As + (wm * 32 + gid) * 132 + tig;
        const float* Bw = Bs + (wn * 16 + gid) * 132 + tig;
        #pragma unroll
        for (int ks = 0; ks < 16; ++ks) {
            const int ko = ks * 8;
            uint32_t af[2][4], bf[2][2];
            #pragma unroll
            for (int t = 0; t < 2; ++t) {
                const float* a = Aw + t * (16 * 132) + ko;
                af[t][0] = __float_as_uint(a[0]);
                af[t][1] = __float_as_uint(a[8 * 132]);
                af[t][2] = __float_as_uint(a[4]);
                af[t][3] = __float_as_uint(a[8 * 132 + 4]);
            }
            #pragma unroll
            for (int j = 0; j < 2; ++j) {
                const float* bp = Bw + j * (8 * 132) + ko;
                bf[j][0] = __float_as_uint(bp[0]);
                bf[j][1] = __float_as_uint(bp[4]);
            }
            #pragma unroll
            for (int t = 0; t < 2; ++t)
                #pragma unroll
                for (int j = 0; j < 2; ++j)
                    MMA_TF32(acc[t][j], af[t], bf[j]);
        }
    }

    // apply state_decay to Yoff on the accumulator
    #pragma unroll
    for (int t = 0; t < 2; ++t) {
        float e0 = eac[wm * 32 + t * 16 + gid];
        float e1 = eac[wm * 32 + t * 16 + gid + 8];
        #pragma unroll
        for (int j = 0; j < 2; ++j) {
            acc[t][j][0] *= e0; acc[t][j][1] *= e0;
            acc[t][j][2] *= e1; acc[t][j][3] *= e1;
        }
    }
    __syncthreads();

    const int cbBase = (b * NC + c) * 4096;
    for (int t = tid; t < 4096; t += 256) {
        int i = t >> 6, jj = t & 63;
        float w = 0.f;
        if (jj <= i) w = tf32r(g_CB[cbBase + i * 64 + jj] * __expf(avec[i] - avec[jj]));
        As[i * 68 + jj] = w;
    }
    const float* xt = &g_xt[(size_t)bch * (HP * CS)];
    for (int t = tid; t < 1024; t += 256) {
        int p = t >> 4, j4 = (t & 15) * 4;
        *(float4*)&Bs[p * 68 + j4] = *(const float4*)&xt[p * CS + j4];
    }
    __syncthreads();

    {
        const float* Aw = As + (wm * 32 + gid) * 68 + tig;
        const float* Bw = Bs + (wn * 16 + gid) * 68 + tig;
        #pragma unroll
        for (int ks = 0; ks < 8; ++ks) {
            const int ko = ks * 8;
            uint32_t af[2][4], bf[2][2];
            #pragma unroll
            for (int t = 0; t < 2; ++t) {
                const float* a = Aw + t * (16 * 68) + ko;
                af[t][0] = __float_as_uint(a[0]);
                af[t][1] = __float_as_uint(a[8 * 68]);
                af[t][2] = __float_as_uint(a[4]);
                af[t][3] = __float_as_uint(a[8 * 68 + 4]);
            }
            #pragma unroll
            for (int j = 0; j < 2; ++j) {
                const float* bp = Bw + j * (8 * 68) + ko;
                bf[j][0] = __float_as_uint(bp[0]);
                bf[j][1] = __float_as_uint(bp[4]);
            }
            #pragma unroll
            for (int t = 0; t < 2; ++t)
                #pragma unroll
                for (int j = 0; j < 2; ++j)
                    MMA_TF32(acc[t][j], af[t], bf[j]);
        }
    }

    #pragma unroll
    for (int t = 0; t < 2; ++t) {
        int i0 = wm * 32 + t * 16 + gid;
        #pragma unroll
        for (int j = 0; j < 2; ++j) {
            int col = h * HP + wn * 16 + j * 8 + tig * 2;
            *(float2*)&g_y[(size_t)(rowBase + i0) * DIEXP + col]
                = make_float2(acc[t][j][0], acc[t][j][1]);
            *(float2*)&g_y[(size_t)(rowBase + i0 + 8) * DIEXP + col]
                = make_float2(acc[t][j][2], acc[t][j][3]);
        }
    }
}

// ---------------- gate + LayerNorm (fast exp, warp-shuffle reductions) -------
__global__ __launch_bounds__(256) void gatenorm_kernel(
    const float* __restrict__ norm_w, const float* __restrict__ norm_b)
{
    const int r = blockIdx.x;
    const int tid = threadIdx.x;
    const int wid = tid >> 5, lane = tid & 31;
    __shared__ float ws1[8];
    __shared__ float ws2[8];

    float v[8];
    float lsum = 0.f;
    #pragma unroll
    for (int e = 0; e < 8; ++e) {
        int col = e * 256 + tid;
        float z  = g_zxbcdt[(size_t)r * DPROJ + col];
        float yv = g_y[(size_t)r * DIEXP + col];
        float val = yv * (z / (1.f + __expf(-z)));
        v[e] = val;
        lsum += val;
    }
    #pragma unroll
    for (int o = 16; o > 0; o >>= 1) lsum += __shfl_xor_sync(0xffffffffu, lsum, o);
    if (lane == 0) ws1[wid] = lsum;
    __syncthreads();
    float tot = 0.f;
    #pragma unroll
    for (int i = 0; i < 8; ++i) tot += ws1[i];
    const float mu = tot / (float)DIEXP;

    float ls2 = 0.f;
    #pragma unroll
    for (int e = 0; e < 8; ++e) { float d = v[e] - mu; ls2 = fmaf(d, d, ls2); }
    #pragma unroll
    for (int o = 16; o > 0; o >>= 1) ls2 += __shfl_xor_sync(0xffffffffu, ls2, o);
    if (lane == 0) ws2[wid] = ls2;
    __syncthreads();
    float tot2 = 0.f;
    #pragma unroll
    for (int i = 0; i < 8; ++i) tot2 += ws2[i];
    const float rstd = rsqrtf(tot2 / (float)DIEXP + 1e-5f);

    #pragma unroll
    for (int e = 0; e < 8; ++e) {
        int col = e * 256 + tid;
        g_y[(size_t)r * DIEXP + col] =
            tf32r((v[e] - mu) * rstd * norm_w[col] + norm_b[col]);
    }
}

// ---------------- launch ----------------
extern "C" void kernel_launch(void* const* d_in, const int* in_sizes, int n_in,
                              void* d_out, int out_size)
{
    const float* u       = (const float*)d_in[0];
    const float* W_in    = (const float*)d_in[1];
    const float* conv_w  = (const float*)d_in[2];
    const float* conv_b  = (const float*)d_in[3];
    const float* dt_bias = (const float*)d_in[4];
    const float* A_log   = (const float*)d_in[5];
    const float* norm_w  = (const float*)d_in[6];
    const float* norm_b  = (const float*)d_in[7];
    const float* W_out   = (const float*)d_in[8];
    float* out = (float*)d_out;

    float *zx = nullptr, *yb = nullptr, *sc = nullptr, *wt = nullptr;
    cudaGetSymbolAddress((void**)&zx, g_zxbcdt);
    cudaGetSymbolAddress((void**)&yb, g_y);
    cudaGetSymbolAddress((void**)&sc, g_states);
    cudaGetSymbolAddress((void**)&wt, g_WT);

    const int GEMM_SMEM   = 2 * GSTG * STG_BYTES;                  // 110592
    const int CB_SMEM     = 2 * 64 * 132 * 4;
    const int STATES_SMEM = (128 + 64 * 68 + 128 * 68) * 4;
    const int Y_SMEM      = (256 + 2 * 64 * 132) * 4;
    cudaFuncSetAttribute(gemm_mma_kernel, cudaFuncAttributeMaxDynamicSharedMemorySize, GEMM_SMEM);
    cudaFuncSetAttribute(cb_kernel,       cudaFuncAttributeMaxDynamicSharedMemorySize, CB_SMEM);
    cudaFuncSetAttribute(states_kernel,   cudaFuncAttributeMaxDynamicSharedMemorySize, STATES_SMEM);
    cudaFuncSetAttribute(y_kernel,        cudaFuncAttributeMaxDynamicSharedMemorySize, Y_SMEM);

    // 0) pre-round u; transpose+round weights
    round_u_kernel<<<(ROWS * DMODEL / 4 + 255) / 256, 256>>>(u, sc);
    transpose_round_kernel<<<dim3((DPROJ + 31) / 32, (DMODEL + 31) / 32), 256>>>(
        W_in, wt, DMODEL, DPROJ);
    transpose_round_kernel<<<dim3((DMODEL + 31) / 32, (DIEXP + 31) / 32), 256>>>(
        W_out, wt + (size_t)DPROJ * DMODEL, DIEXP, DMODEL);

    // 1) zxbcdt = u @ W_in
    gemm_mma_kernel<<<dim3((DPROJ + 127) / 128, ROWS / 128), 256, GEMM_SMEM>>>(
        sc, wt, zx, ROWS, DPROJ, DMODEL);
    // 2) dt, conv (folds dt; fast exp), cumsums
    dt_kernel<<<(ROWS * NH + 255) / 256, 256>>>(dt_bias, A_log);
    conv_silu_kernel<<<(CONVD * (ROWS / 4) + 255) / 256, 256>>>(conv_w, conv_b);
    acum_kernel<<<(NBCH + 255) / 256, 256>>>();
    // 4) CB gram (mma)
    cb_kernel<<<BSZ * NC, 256, CB_SMEM>>>();
    // 5) per-chunk states (mma)
    states_kernel<<<dim3(NC, BSZ, NH), 256, STATES_SMEM>>>();
    // 6) inter-chunk recurrence (float4, rounded states_in)
    recur_kernel<<<BSZ * NH * 8, 256>>>();
    // 7) Y (mma, copy-only staging)
    y_kernel<<<dim3(NC, BSZ, NH), 256, Y_SMEM>>>();
    // 8) gate + layernorm
    gatenorm_kernel<<<ROWS, 256>>>(norm_w, norm_b);
    // 9) out = y @ W_out
    gemm_mma_kernel<<<dim3(DMODEL / 128, ROWS / 128), 256, GEMM_SMEM>>>(
        yb, wt + (size_t)DPROJ * DMODEL, out, ROWS, DMODEL, DIEXP);
}

// round 14
// speedup vs baseline: 1.0383x; 1.0383x over previous
#include <cuda_runtime.h>
#include <math.h>
#include <stdint.h>

// ---------------- problem constants ----------------
#define BSZ    2
#define LSEQ   4096
#define DMODEL 1024
#define DIEXP  2048
#define NH     32
#define HP     64
#define DS     128
#define CS     64
#define NC     64
#define DPROJ  4384
#define CONVD  2304
#define ROWS   8192
#define NBCH   (BSZ * NC * NH)          // 4096

// ---------------- device scratch ----------------
__device__ float g_zxbcdt[(size_t)ROWS * DPROJ];
__device__ float g_xt    [(size_t)NBCH * HP * CS];        // (x*dt)^T per (b,c,h): [p][s], fp32
__device__ float g_bc    [(size_t)ROWS * 256];            // [row][B(128)|C(128)], tf32
__device__ float g_bt    [(size_t)BSZ * NC * DS * CS];    // B^T per (b,c): [n][s], tf32
__device__ float g_acum  [NBCH * CS];
__device__ float g_dt    [ROWS * NH];
__device__ float g_adt   [ROWS * NH];
__device__ float g_CB    [BSZ * NC * CS * CS];
__device__ float g_states[(size_t)NBCH * HP * DS];        // head reused as rounded-u scratch
__device__ float g_dchunk[NBCH];
__device__ float g_y     [(size_t)ROWS * DIEXP];
__device__ float g_WT    [(size_t)DPROJ * DMODEL + (size_t)DMODEL * DIEXP];

// ---------------- helpers ----------------
__device__ __forceinline__ uint32_t f2tf32(float x) {
    uint32_t r;
    asm("cvt.rna.tf32.f32 %0, %1;" : "=r"(r) : "f"(x));
    return r;
}
__device__ __forceinline__ float tf32r(float x) { return __uint_as_float(f2tf32(x)); }

__device__ __forceinline__ uint32_t smem_u32(const void* p) {
    uint32_t a;
    asm("{ .reg .u64 t; cvta.to.shared.u64 t, %1; cvt.u32.u64 %0, t; }" : "=r"(a) : "l"(p));
    return a;
}
__device__ __forceinline__ void cp_async16(uint32_t dst, const void* src) {
    asm volatile("cp.async.cg.shared.global [%0], [%1], 16;" :: "r"(dst), "l"(src) : "memory");
}
#define MMA_TF32(acc, af, bf)                                               \
    asm volatile(                                                           \
        "mma.sync.aligned.m16n8k8.row.col.f32.tf32.tf32.f32 "               \
        "{%0,%1,%2,%3}, {%4,%5,%6,%7}, {%8,%9}, {%0,%1,%2,%3};\n"           \
        : "+f"((acc)[0]), "+f"((acc)[1]), "+f"((acc)[2]), "+f"((acc)[3])    \
        : "r"((af)[0]), "r"((af)[1]), "r"((af)[2]), "r"((af)[3]),           \
          "r"((bf)[0]), "r"((bf)[1]))

// =====================================================================
// tf32 mma.sync dense GEMM — EXACT R8 proven version (do not touch)
// =====================================================================
#define GSTG 3
#define ROWB 144
#define STG_BYTES (128 * ROWB)

__global__ __launch_bounds__(256) void gemm_mma_kernel(
    const float* __restrict__ A, const float* __restrict__ BT,
    float* __restrict__ C, int M, int N, int K)
{
    extern __shared__ char sm[];
    const uint32_t sb = smem_u32(sm);
    const int tid  = threadIdx.x;
    const int wid  = tid >> 5, lane = tid & 31;
    const int gid  = lane >> 2, tig = lane & 3;
    const int wm   = wid >> 1,  wn  = wid & 1;
    const int mBase = blockIdx.y * 128, nBase = blockIdx.x * 128;

    float acc[2][8][4];
    #pragma unroll
    for (int t = 0; t < 2; ++t)
        #pragma unroll
        for (int j = 0; j < 8; ++j)
            #pragma unroll
            for (int e = 0; e < 4; ++e) acc[t][j][e] = 0.f;

    const int KT = K >> 5;
    const int lrow = tid >> 3, lc16 = tid & 7;
    const int aOff = (wm * 32 + gid) * ROWB + tig * 4;
    const int bOff = (wn * 64 + gid) * ROWB + tig * 4;

    auto load_stage = [&](int kt, int s) {
        const int k0 = kt << 5;
        const uint32_t ab = sb + s * STG_BYTES;
        const uint32_t bb = sb + GSTG * STG_BYTES + s * STG_BYTES;
        #pragma unroll
        for (int i = 0; i < 4; ++i) {
            int row = lrow + i * 32;
            cp_async16(ab + row * ROWB + lc16 * 16,
                       A + (size_t)(mBase + row) * K + k0 + lc16 * 4);
        }
        #pragma unroll
        for (int i = 0; i < 4; ++i) {
            int row = lrow + i * 32;
            int nr = nBase + row; if (nr >= N) nr = N - 1;
            cp_async16(bb + row * ROWB + lc16 * 16,
                       BT + (size_t)nr * K + k0 + lc16 * 4);
        }
        asm volatile("cp.async.commit_group;" ::: "memory");
    };

    load_stage(0, 0);
    if (KT > 1) load_stage(1, 1);

    for (int kt = 0; kt < KT; ++kt) {
        const int s = kt % GSTG;
        asm volatile("cp.async.wait_group 1;" ::: "memory");
        __syncthreads();

        const char* As = sm + s * STG_BYTES + aOff;
        const char* Bs = sm + GSTG * STG_BYTES + s * STG_BYTES + bOff;

        #pragma unroll
        for (int ks = 0; ks < 4; ++ks) {
            const int kb = ks * 32;
            uint32_t af[2][4];
            #pragma unroll
            for (int t = 0; t < 2; ++t) {
                const char* a = As + t * (16 * ROWB) + kb;
                af[t][0] = *(const uint32_t*)(a);
                af[t][1] = *(const uint32_t*)(a + 8 * ROWB);
                af[t][2] = *(const uint32_t*)(a + 16);
                af[t][3] = *(const uint32_t*)(a + 8 * ROWB + 16);
            }
            uint32_t bf[8][2];
            #pragma unroll
            for (int j = 0; j < 8; ++j) {
                const char* bp = Bs + j * (8 * ROWB) + kb;
                bf[j][0] = *(const uint32_t*)(bp);
                bf[j][1] = *(const uint32_t*)(bp + 16);
            }
            #pragma unroll
            for (int t = 0; t < 2; ++t)
                #pragma unroll
                for (int j = 0; j < 8; ++j)
                    MMA_TF32(acc[t][j], af[t], bf[j]);
        }
        if (kt + 2 < KT) load_stage(kt + 2, (kt + 2) % GSTG);
    }

    #pragma unroll
    for (int t = 0; t < 2; ++t) {
        int r0 = mBase + wm * 32 + t * 16 + gid;
        #pragma unroll
        for (int j = 0; j < 8; ++j) {
            int c0 = nBase + wn * 64 + j * 8 + tig * 2;
            if (c0 + 1 < N) {
                *(float2*)&C[(size_t)r0 * N + c0]       = make_float2(acc[t][j][0], acc[t][j][1]);
                *(float2*)&C[(size_t)(r0 + 8) * N + c0] = make_float2(acc[t][j][2], acc[t][j][3]);
            } else if (c0 < N) {
                C[(size_t)r0 * N + c0]       = acc[t][j][0];
                C[(size_t)(r0 + 8) * N + c0] = acc[t][j][2];
            }
        }
    }
}

// ---------------- pre-rounding / weight transpose ----------------
__global__ __launch_bounds__(256) void round_u_kernel(const float* __restrict__ u, float* __restrict__ o)
{
    int idx = blockIdx.x * 256 + threadIdx.x;
    if (idx < ROWS * DMODEL / 4) {
        float4 v = ((const float4*)u)[idx];
        v.x = tf32r(v.x); v.y = tf32r(v.y); v.z = tf32r(v.z); v.w = tf32r(v.w);
        ((float4*)o)[idx] = v;
    }
}

__global__ __launch_bounds__(256) void transpose_round_kernel(
    const float* __restrict__ W, float* __restrict__ WT, int K, int N)
{
    __shared__ float tile[32][33];
    const int bx = blockIdx.x * 32, by = blockIdx.y * 32;
    const int x = threadIdx.x & 31, y = threadIdx.x >> 5;
    #pragma unroll
    for (int i = 0; i < 32; i += 8) {
        int k = by + y + i, n = bx + x;
        tile[y + i][x] = (k < K && n < N) ? W[(size_t)k * N + n] : 0.f;
    }
    __syncthreads();
    #pragma unroll
    for (int i = 0; i < 32; i += 8) {
        int n = bx + y + i, k = by + x;
        if (n < N && k < K) WT[(size_t)n * K + k] = tf32r(tile[x][y + i]);
    }
}

// ---------------- dt / A*dt (runs BEFORE conv so conv can fold dt into x) ----
__global__ __launch_bounds__(256) void dt_kernel(
    const float* __restrict__ dt_bias, const float* __restrict__ A_log)
{
    int idx = blockIdx.x * 256 + threadIdx.x;
    if (idx >= ROWS * NH) return;
    int r = idx >> 5;
    int h = idx & 31;
    float x = g_zxbcdt[(size_t)r * DPROJ + (DPROJ - NH) + h] + dt_bias[h];
    float sp = (x > 20.f) ? x : log1pf(expf(x));   // keep precise softplus
    g_dt[idx]  = sp;
    g_adt[idx] = -expf(A_log[h]) * sp;
}

// ---------------- conv + SiLU -> mma-ready layouts; x pre-scaled by dt -------
__global__ __launch_bounds__(256) void conv_silu_kernel(
    const float* __restrict__ conv_w, const float* __restrict__ conv_b)
{
    int idx = blockIdx.x * 256 + threadIdx.x;
    if (idx >= CONVD * (ROWS / 4)) return;
    const int ch = idx % CONVD;
    const int r4 = idx / CONVD;
    const int r0 = r4 * 4;
    const int b  = r0 >> 12;
    const int l0 = r0 & (LSEQ - 1);

    const float w0 = conv_w[ch * 4 + 0], w1 = conv_w[ch * 4 + 1];
    const float w2 = conv_w[ch * 4 + 2], w3 = conv_w[ch * 4 + 3];
    const float bias = conv_b[ch];

    float in[7];
    #pragma unroll
    for (int i = 0; i < 7; ++i) {
        int l = l0 - 3 + i;
        in[i] = (l >= 0) ? g_zxbcdt[(size_t)(r0 - 3 + i) * DPROJ + DIEXP + ch] : 0.f;
    }
    float o[4];
    #pragma unroll
    for (int k = 0; k < 4; ++k) {
        float a = bias;
        a = fmaf(in[k],     w0, a);
        a = fmaf(in[k + 1], w1, a);
        a = fmaf(in[k + 2], w2, a);
        a = fmaf(in[k + 3], w3, a);
        o[k] = a / (1.f + __expf(-a));
    }

    const int c  = l0 >> 6;
    const int s0 = l0 & 63;

    if (ch < DIEXP) {
        const int h = ch >> 6, p = ch & 63;
        // fold dt: xt stores x * dt (broadcast loads, same addr across ~64 lanes)
        #pragma unroll
        for (int k = 0; k < 4; ++k)
            o[k] *= g_dt[(r0 + k) * NH + h];
        const size_t base = (((size_t)((b * NC + c) * NH + h)) * HP + p) * CS + s0;
        *(float4*)&g_xt[base] = make_float4(o[0], o[1], o[2], o[3]);
    } else {
        const int cc = ch - DIEXP;   // 0..255
        #pragma unroll
        for (int k = 0; k < 4; ++k)
            g_bc[(size_t)(r0 + k) * 256 + cc] = tf32r(o[k]);
        if (cc < DS) {
            const size_t base = ((size_t)(b * NC + c) * DS + cc) * CS + s0;
            *(float4*)&g_bt[base] = make_float4(tf32r(o[0]), tf32r(o[1]), tf32r(o[2]), tf32r(o[3]));
        }
    }
}

// ---------------- per-(b,c,h) cumsum of adt ----------------
__global__ __launch_bounds__(256) void acum_kernel()
{
    int bch = blockIdx.x * 256 + threadIdx.x;
    if (bch >= NBCH) return;
    int h = bch & 31;
    int c = (bch >> 5) & 63;
    int b = bch >> 11;
    int rowBase = b * LSEQ + c * CS;
    float a = 0.f;
    #pragma unroll 8
    for (int s = 0; s < CS; ++s) {
        a += g_adt[(rowBase + s) * NH + h];
        g_acum[bch * CS + s] = a;
    }
    g_dchunk[bch] = __expf(a);
}

// ---------------- CB gram via mma ----------------
__global__ __launch_bounds__(256) void cb_kernel()
{
    extern __shared__ float dsm[];
    float* As = dsm;
    float* Bs = dsm + 64 * 132;
    const int bc = blockIdx.x;
    const int rowBase = bc * CS;
    const int tid = threadIdx.x;
    const int wid = tid >> 5, lane = tid & 31;
    const int gid = lane >> 2, tig = lane & 3;
    const int wm = wid >> 2, wn = wid & 3;

    for (int t = tid; t < 2048; t += 256) {
        int i = t >> 5, n4 = (t & 31) * 4;
        *(float4*)&As[i * 132 + n4] = *(const float4*)&g_bc[(size_t)(rowBase + i) * 256 + 128 + n4];
        *(float4*)&Bs[i * 132 + n4] = *(const float4*)&g_bc[(size_t)(rowBase + i) * 256 + n4];
    }
    __syncthreads();

    float acc[2][2][4];
    #pragma unroll
    for (int t = 0; t < 2; ++t)
        #pragma unroll
        for (int j = 0; j < 2; ++j)
            #pragma unroll
            for (int e = 0; e < 4; ++e) acc[t][j][e] = 0.f;

    const float* Aw = As + (wm * 32 + gid) * 132 + tig;
    const float* Bw = Bs + (wn * 16 + gid) * 132 + tig;
    #pragma unroll
    for (int ks = 0; ks < 16; ++ks) {
        const int ko = ks * 8;
        uint32_t af[2][4], bf[2][2];
        #pragma unroll
        for (int t = 0; t < 2; ++t) {
            const float* a = Aw + t * (16 * 132) + ko;
            af[t][0] = __float_as_uint(a[0]);
            af[t][1] = __float_as_uint(a[8 * 132]);
            af[t][2] = __float_as_uint(a[4]);
            af[t][3] = __float_as_uint(a[8 * 132 + 4]);
        }
        #pragma unroll
        for (int j = 0; j < 2; ++j) {
            const float* bp = Bw + j * (8 * 132) + ko;
            bf[j][0] = __float_as_uint(bp[0]);
            bf[j][1] = __float_as_uint(bp[4]);
        }
        #pragma unroll
        for (int t = 0; t < 2; ++t)
            #pragma unroll
            for (int j = 0; j < 2; ++j)
                MMA_TF32(acc[t][j], af[t], bf[j]);
    }

    #pragma unroll
    for (int t = 0; t < 2; ++t) {
        int i0 = wm * 32 + t * 16 + gid;
        #pragma unroll
        for (int j = 0; j < 2; ++j) {
            int j0 = wn * 16 + j * 8 + tig * 2;
            *(float2*)&g_CB[bc * 4096 + i0 * 64 + j0]       = make_float2(acc[t][j][0], acc[t][j][1]);
            *(float2*)&g_CB[bc * 4096 + (i0 + 8) * 64 + j0] = make_float2(acc[t][j][2], acc[t][j][3]);
        }
    }
}

// ---------------- states via mma (xt already includes dt) ----------------
__global__ __launch_bounds__(256) void states_kernel()
{
    extern __shared__ float dsm[];
    float* wv = dsm;
    float* As = dsm + 128;
    float* Bs = As + 64 * 68;
    const int c = blockIdx.x, b = blockIdx.y, h = blockIdx.z;
    const int bch = (b * NC + c) * NH + h;
    const int tid = threadIdx.x;
    const int wid = tid >> 5, lane = tid & 31;
    const int gid = lane >> 2, tig = lane & 3;
    const int wm = wid >> 2, wn = wid & 3;

    if (tid < CS) {
        float aend = g_acum[bch * CS + CS - 1];
        float ac   = g_acum[bch * CS + tid];
        wv[tid] = __expf(aend - ac);
    }
    __syncthreads();

    const float* xt = &g_xt[(size_t)bch * (HP * CS)];
    for (int t = tid; t < 1024; t += 256) {
        int p = t >> 4, s4 = (t & 15) * 4;
        float4 v = *(const float4*)&xt[p * CS + s4];
        v.x = tf32r(v.x * wv[s4 + 0]);
        v.y = tf32r(v.y * wv[s4 + 1]);
        v.z = tf32r(v.z * wv[s4 + 2]);
        v.w = tf32r(v.w * wv[s4 + 3]);
        *(float4*)&As[p * 68 + s4] = v;
    }
    const float* bt = &g_bt[(size_t)(b * NC + c) * (DS * CS)];
    for (int t = tid; t < 2048; t += 256) {
        int n = t >> 4, s4 = (t & 15) * 4;
        *(float4*)&Bs[n * 68 + s4] = *(const float4*)&bt[n * CS + s4];
    }
    __syncthreads();

    float acc[2][4][4];
    #pragma unroll
    for (int t = 0; t < 2; ++t)
        #pragma unroll
        for (int j = 0; j < 4; ++j)
            #pragma unroll
            for (int e = 0; e < 4; ++e) acc[t][j][e] = 0.f;

    const float* Aw = As + (wm * 32 + gid) * 68 + tig;
    const float* Bw = Bs + (wn * 32 + gid) * 68 + tig;
    #pragma unroll
    for (int ks = 0; ks < 8; ++ks) {
        const int ko = ks * 8;
        uint32_t af[2][4], bf[4][2];
        #pragma unroll
        for (int t = 0; t < 2; ++t) {
            const float* a = Aw + t * (16 * 68) + ko;
            af[t][0] = __float_as_uint(a[0]);
            af[t][1] = __float_as_uint(a[8 * 68]);
            af[t][2] = __float_as_uint(a[4]);
            af[t][3] = __float_as_uint(a[8 * 68 + 4]);
        }
        #pragma unroll
        for (int j = 0; j < 4; ++j) {
            const float* bp = Bw + j * (8 * 68) + ko;
            bf[j][0] = __float_as_uint(bp[0]);
            bf[j][1] = __float_as_uint(bp[4]);
        }
        #pragma unroll
        for (int t = 0; t < 2; ++t)
            #pragma unroll
            for (int j = 0; j < 4; ++j)
                MMA_TF32(acc[t][j], af[t], bf[j]);
    }

    float* S = &g_states[(size_t)bch * (HP * DS)];
    #pragma unroll
    for (int t = 0; t < 2; ++t) {
        int p0 = wm * 32 + t * 16 + gid;
        #pragma unroll
        for (int j = 0; j < 4; ++j) {
            int n0 = wn * 32 + j * 8 + tig * 2;
            *(float2*)&S[p0 * DS + n0]       = make_float2(acc[t][j][0], acc[t][j][1]);
            *(float2*)&S[(p0 + 8) * DS + n0] = make_float2(acc[t][j][2], acc[t][j][3]);
        }
    }
}

// ---------------- inter-chunk recurrence (float4, plain fp32 writes) ---------
__global__ __launch_bounds__(256) void recur_kernel()
{
    const int bid = blockIdx.x;          // 0 .. BSZ*NH*8-1
    const int bh  = bid >> 3;            // b*NH + h
    const int eo4 = ((bid & 7) << 8) + threadIdx.x;   // float4 index 0..2047
    const int b = bh >> 5, h = bh & 31;

    float4 S = make_float4(0.f, 0.f, 0.f, 0.f);
    for (int c = 0; c < NC; ++c) {
        int bch = (b * NC + c) * NH + h;
        float d = g_dchunk[bch];
        float4* ptr = (float4*)&g_states[(size_t)bch * (HP * DS)] + eo4;
        float4 t = *ptr;
        *ptr = S;
        S.x = fmaf(d, S.x, t.x);
        S.y = fmaf(d, S.y, t.y);
        S.z = fmaf(d, S.z, t.z);
        S.w = fmaf(d, S.w, t.w);
    }
}

// ---------------- Y via mma: Yoff (K=128) + Yd (K=64); xt includes dt --------
__global__ __launch_bounds__(256) void y_kernel()
{
    extern __shared__ float dsm[];
    float* avec = dsm;
    float* eac  = dsm + 64;
    float* As   = dsm + 256;
    float* Bs   = As + 64 * 132;
    const int c = blockIdx.x, b = blockIdx.y, h = blockIdx.z;
    const int bch = (b * NC + c) * NH + h;
    const int rowBase = b * LSEQ + c * CS;
    const int tid = threadIdx.x;
    const int wid = tid >> 5, lane = tid & 31;
    const int gid = lane >> 2, tig = lane & 3;
    const int wm = wid >> 2, wn = wid & 3;

    if (tid < CS) {
        float ac = g_acum[bch * CS + tid];
        avec[tid] = ac;
        eac[tid]  = __expf(ac);
    }
    __syncthreads();

    const float* Sin = &g_states[(size_t)bch * (HP * DS)];
    for (int t = tid; t < 2048; t += 256) {
        int i = t >> 5, n4 = (t & 31) * 4;
        float e = eac[i];
        float4 cv = *(const float4*)&g_bc[(size_t)(rowBase + i) * 256 + 128 + n4];
        cv.x = tf32r(cv.x * e); cv.y = tf32r(cv.y * e);
        cv.z = tf32r(cv.z * e); cv.w = tf32r(cv.w * e);
        *(float4*)&As[i * 132 + n4] = cv;
        float4 sv = *(const float4*)&Sin[i * DS + n4];
        sv.x = tf32r(sv.x); sv.y = tf32r(sv.y);
        sv.z = tf32r(sv.z); sv.w = tf32r(sv.w);
        *(float4*)&Bs[i * 132 + n4] = sv;
    }
    __syncthreads();

    float acc[2][2][4];
    #pragma unroll
    for (int t = 0; t < 2; ++t)
        #pragma unroll
        for (int j = 0; j < 2; ++j)
            #pragma unroll
            for (int e = 0; e < 4; ++e) acc[t][j][e] = 0.f;

    {
        const float* Aw = As + (wm * 32 + gid) * 132 + tig;
        const float* Bw = Bs + (wn * 16 + gid) * 132 + tig;
        #pragma unroll
        for (int ks = 0; ks < 16; ++ks) {
            const int ko = ks * 8;
            uint32_t af[2][4], bf[2][2];
            #pragma unroll
            for (int t = 0; t < 2; ++t) {
                const float* a = Aw + t * (16 * 132) + ko;
                af[t][0] = __float_as_uint(a[0]);
                af[t][1] = __float_as_uint(a[8 * 132]);
                af[t][2] = __float_as_uint(a[4]);
                af[t][3] = __float_as_uint(a[8 * 132 + 4]);
            }
            #pragma unroll
            for (int j = 0; j < 2; ++j) {
                const float* bp = Bw + j * (8 * 132) + ko;
                bf[j][0] = __float_as_uint(bp[0]);
                bf[j][1] = __float_as_uint(bp[4]);
            }
            #pragma unroll
            for (int t = 0; t < 2; ++t)
                #pragma unroll
                for (int j = 0; j < 2; ++j)
                    MMA_TF32(acc[t][j], af[t], bf[j]);
        }
    }
    __syncthreads();

    const int cbBase = (b * NC + c) * 4096;
    for (int t = tid; t < 4096; t += 256) {
        int i = t >> 6, jj = t & 63;
        float w = 0.f;
        if (jj <= i) w = tf32r(g_CB[cbBase + i * 64 + jj] * __expf(avec[i] - avec[jj]));
        As[i * 68 + jj] = w;
    }
    const float* xt = &g_xt[(size_t)bch * (HP * CS)];
    for (int t = tid; t < 1024; t += 256) {
        int p = t >> 4, j4 = (t & 15) * 4;
        float4 v = *(const float4*)&xt[p * CS + j4];
        v.x = tf32r(v.x); v.y = tf32r(v.y);
        v.z = tf32r(v.z); v.w = tf32r(v.w);
        *(float4*)&Bs[p * 68 + j4] = v;
    }
    __syncthreads();

    {
        const float* Aw = As + (wm * 32 + gid) * 68 + tig;
        const float* Bw = Bs + (wn * 16 + gid) * 68 + tig;
        #pragma unroll
        for (int ks = 0; ks < 8; ++ks) {
            const int ko = ks * 8;
            uint32_t af[2][4], bf[2][2];
            #pragma unroll
            for (int t = 0; t < 2; ++t) {
                const float* a = Aw + t * (16 * 68) + ko;
                af[t][0] = __float_as_uint(a[0]);
                af[t][1] = __float_as_uint(a[8 * 68]);
                af[t][2] = __float_as_uint(a[4]);
                af[t][3] = __float_as_uint(a[8 * 68 + 4]);
            }
            #pragma unroll
            for (int j = 0; j < 2; ++j) {
                const float* bp = Bw + j * (8 * 68) + ko;
                bf[j][0] = __float_as_uint(bp[0]);
                bf[j][1] = __float_as_uint(bp[4]);
            }
            #pragma unroll
            for (int t = 0; t < 2; ++t)
                #pragma unroll
                for (int j = 0; j < 2; ++j)
                    MMA_TF32(acc[t][j], af[t], bf[j]);
        }
    }

    #pragma unroll
    for (int t = 0; t < 2; ++t) {
        int i0 = wm * 32 + t * 16 + gid;
        #pragma unroll
        for (int j = 0; j < 2; ++j) {
            int col = h * HP + wn * 16 + j * 8 + tig * 2;
            *(float2*)&g_y[(size_t)(rowBase + i0) * DIEXP + col]
                = make_float2(acc[t][j][0], acc[t][j][1]);
            *(float2*)&g_y[(size_t)(rowBase + i0 + 8) * DIEXP + col]
                = make_float2(acc[t][j][2], acc[t][j][3]);
        }
    }
}

// ---------------- gate + LayerNorm (warp-shuffle reductions) ----------------
__global__ __launch_bounds__(256) void gatenorm_kernel(
    const float* __restrict__ norm_w, const float* __restrict__ norm_b)
{
    const int r = blockIdx.x;
    const int tid = threadIdx.x;
    const int wid = tid >> 5, lane = tid & 31;
    __shared__ float ws1[8];
    __shared__ float ws2[8];

    float v[8];
    float lsum = 0.f;
    #pragma unroll
    for (int e = 0; e < 8; ++e) {
        int col = e * 256 + tid;
        float z  = g_zxbcdt[(size_t)r * DPROJ + col];
        float yv = g_y[(size_t)r * DIEXP + col];
        float val = yv * (z / (1.f + __expf(-z)));
        v[e] = val;
        lsum += val;
    }
    #pragma unroll
    for (int o = 16; o > 0; o >>= 1) lsum += __shfl_xor_sync(0xffffffffu, lsum, o);
    if (lane == 0) ws1[wid] = lsum;
    __syncthreads();
    float tot = 0.f;
    #pragma unroll
    for (int i = 0; i < 8; ++i) tot += ws1[i];
    const float mu = tot / (float)DIEXP;

    float ls2 = 0.f;
    #pragma unroll
    for (int e = 0; e < 8; ++e) { float d = v[e] - mu; ls2 = fmaf(d, d, ls2); }
    #pragma unroll
    for (int o = 16; o > 0; o >>= 1) ls2 += __shfl_xor_sync(0xffffffffu, ls2, o);
    if (lane == 0) ws2[wid] = ls2;
    __syncthreads();
    float tot2 = 0.f;
    #pragma unroll
    for (int i = 0; i < 8; ++i) tot2 += ws2[i];
    const float rstd = rsqrtf(tot2 / (float)DIEXP + 1e-5f);

    #pragma unroll
    for (int e = 0; e < 8; ++e) {
        int col = e * 256 + tid;
        g_y[(size_t)r * DIEXP + col] =
            tf32r((v[e] - mu) * rstd * norm_w[col] + norm_b[col]);
    }
}

// ---------------- launch ----------------
extern "C" void kernel_launch(void* const* d_in, const int* in_sizes, int n_in,
                              void* d_out, int out_size)
{
    const float* u       = (const float*)d_in[0];
    const float* W_in    = (const float*)d_in[1];
    const float* conv_w  = (const float*)d_in[2];
    const float* conv_b  = (const float*)d_in[3];
    const float* dt_bias = (const float*)d_in[4];
    const float* A_log   = (const float*)d_in[5];
    const float* norm_w  = (const float*)d_in[6];
    const float* norm_b  = (const float*)d_in[7];
    const float* W_out   = (const float*)d_in[8];
    float* out = (float*)d_out;

    float *zx = nullptr, *yb = nullptr, *sc = nullptr, *wt = nullptr;
    cudaGetSymbolAddress((void**)&zx, g_zxbcdt);
    cudaGetSymbolAddress((void**)&yb, g_y);
    cudaGetSymbolAddress((void**)&sc, g_states);
    cudaGetSymbolAddress((void**)&wt, g_WT);

    const int GEMM_SMEM   = 2 * GSTG * STG_BYTES;                  // 110592
    const int CB_SMEM     = 2 * 64 * 132 * 4;
    const int STATES_SMEM = (128 + 64 * 68 + 128 * 68) * 4;
    const int Y_SMEM      = (256 + 2 * 64 * 132) * 4;
    cudaFuncSetAttribute(gemm_mma_kernel, cudaFuncAttributeMaxDynamicSharedMemorySize, GEMM_SMEM);
    cudaFuncSetAttribute(cb_kernel,       cudaFuncAttributeMaxDynamicSharedMemorySize, CB_SMEM);
    cudaFuncSetAttribute(states_kernel,   cudaFuncAttributeMaxDynamicSharedMemorySize, STATES_SMEM);
    cudaFuncSetAttribute(y_kernel,        cudaFuncAttributeMaxDynamicSharedMemorySize, Y_SMEM);

    // 0) pre-round u; transpose+round weights
    round_u_kernel<<<(ROWS * DMODEL / 4 + 255) / 256, 256>>>(u, sc);
    transpose_round_kernel<<<dim3((DPROJ + 31) / 32, (DMODEL + 31) / 32), 256>>>(
        W_in, wt, DMODEL, DPROJ);
    transpose_round_kernel<<<dim3((DMODEL + 31) / 32, (DIEXP + 31) / 32), 256>>>(
        W_out, wt + (size_t)DPROJ * DMODEL, DIEXP, DMODEL);

    // 1) zxbcdt = u @ W_in
    gemm_mma_kernel<<<dim3((DPROJ + 127) / 128, ROWS / 128), 256, GEMM_SMEM>>>(
        sc, wt, zx, ROWS, DPROJ, DMODEL);
    // 2) dt first (conv folds dt into x), then conv, then cumsums
    dt_kernel<<<(ROWS * NH + 255) / 256, 256>>>(dt_bias, A_log);
    conv_silu_kernel<<<(CONVD * (ROWS / 4) + 255) / 256, 256>>>(conv_w, conv_b);
    acum_kernel<<<(NBCH + 255) / 256, 256>>>();
    // 4) CB gram (mma)
    cb_kernel<<<BSZ * NC, 256, CB_SMEM>>>();
    // 5) per-chunk states (mma)
    states_kernel<<<dim3(NC, BSZ, NH), 256, STATES_SMEM>>>();
    // 6) inter-chunk recurrence (float4)
    recur_kernel<<<BSZ * NH * 8, 256>>>();
    // 7) Y (mma)
    y_kernel<<<dim3(NC, BSZ, NH), 256, Y_SMEM>>>();
    // 8) gate + layernorm (warp-shuffle)
    gatenorm_kernel<<<ROWS, 256>>>(norm_w, norm_b);
    // 9) out = y @ W_out
    gemm_mma_kernel<<<dim3(DMODEL / 128, ROWS / 128), 256, GEMM_SMEM>>>(
        yb, wt + (size_t)DPROJ * DMODEL, out, ROWS, DMODEL, DIEXP);
}

// round 16
// speedup vs baseline: 1.0536x; 1.0147x over previous
#include <cuda_runtime.h>
#include <math.h>
#include <stdint.h>

// ---------------- problem constants ----------------
#define BSZ    2
#define LSEQ   4096
#define DMODEL 1024
#define DIEXP  2048
#define NH     32
#define HP     64
#define DS     128
#define CS     64
#define NC     64
#define DPROJ  4384
#define CONVD  2304
#define ROWS   8192
#define NBCH   (BSZ * NC * NH)          // 4096

// ---------------- device scratch ----------------
__device__ float g_zxbcdt[(size_t)ROWS * DPROJ];
__device__ float g_xt    [(size_t)NBCH * HP * CS];        // (x*dt)^T per (b,c,h): [p][s], fp32
__device__ float g_bc    [(size_t)ROWS * 256];            // [row][B(128)|C(128)], tf32
__device__ float g_bt    [(size_t)BSZ * NC * DS * CS];    // B^T per (b,c): [n][s], tf32
__device__ float g_acum  [NBCH * CS];
__device__ float g_dt    [ROWS * NH];
__device__ float g_adt   [ROWS * NH];
__device__ float g_CB    [BSZ * NC * CS * CS];
__device__ float g_states[(size_t)NBCH * HP * DS];        // head reused as rounded-u scratch
__device__ float g_dchunk[NBCH];
__device__ float g_y     [(size_t)ROWS * DIEXP];
__device__ float g_WT    [(size_t)DPROJ * DMODEL + (size_t)DMODEL * DIEXP];

// ---------------- helpers ----------------
__device__ __forceinline__ uint32_t f2tf32(float x) {
    uint32_t r;
    asm("cvt.rna.tf32.f32 %0, %1;" : "=r"(r) : "f"(x));
    return r;
}
__device__ __forceinline__ float tf32r(float x) { return __uint_as_float(f2tf32(x)); }

__device__ __forceinline__ uint32_t smem_u32(const void* p) {
    uint32_t a;
    asm("{ .reg .u64 t; cvta.to.shared.u64 t, %1; cvt.u32.u64 %0, t; }" : "=r"(a) : "l"(p));
    return a;
}
__device__ __forceinline__ void cp_async16(uint32_t dst, const void* src) {
    asm volatile("cp.async.cg.shared.global [%0], [%1], 16;" :: "r"(dst), "l"(src) : "memory");
}
#define MMA_TF32(acc, af, bf)                                               \
    asm volatile(                                                           \
        "mma.sync.aligned.m16n8k8.row.col.f32.tf32.tf32.f32 "               \
        "{%0,%1,%2,%3}, {%4,%5,%6,%7}, {%8,%9}, {%0,%1,%2,%3};\n"           \
        : "+f"((acc)[0]), "+f"((acc)[1]), "+f"((acc)[2]), "+f"((acc)[3])    \
        : "r"((af)[0]), "r"((af)[1]), "r"((af)[2]), "r"((af)[3]),           \
          "r"((bf)[0]), "r"((bf)[1]))

// =====================================================================
// tf32 mma.sync dense GEMM — EXACT R8 proven version (do not touch)
// =====================================================================
#define GSTG 3
#define ROWB 144
#define STG_BYTES (128 * ROWB)

__global__ __launch_bounds__(256) void gemm_mma_kernel(
    const float* __restrict__ A, const float* __restrict__ BT,
    float* __restrict__ C, int M, int N, int K)
{
    extern __shared__ char sm[];
    const uint32_t sb = smem_u32(sm);
    const int tid  = threadIdx.x;
    const int wid  = tid >> 5, lane = tid & 31;
    const int gid  = lane >> 2, tig = lane & 3;
    const int wm   = wid >> 1,  wn  = wid & 1;
    const int mBase = blockIdx.y * 128, nBase = blockIdx.x * 128;

    float acc[2][8][4];
    #pragma unroll
    for (int t = 0; t < 2; ++t)
        #pragma unroll
        for (int j = 0; j < 8; ++j)
            #pragma unroll
            for (int e = 0; e < 4; ++e) acc[t][j][e] = 0.f;

    const int KT = K >> 5;
    const int lrow = tid >> 3, lc16 = tid & 7;
    const int aOff = (wm * 32 + gid) * ROWB + tig * 4;
    const int bOff = (wn * 64 + gid) * ROWB + tig * 4;

    auto load_stage = [&](int kt, int s) {
        const int k0 = kt << 5;
        const uint32_t ab = sb + s * STG_BYTES;
        const uint32_t bb = sb + GSTG * STG_BYTES + s * STG_BYTES;
        #pragma unroll
        for (int i = 0; i < 4; ++i) {
            int row = lrow + i * 32;
            cp_async16(ab + row * ROWB + lc16 * 16,
                       A + (size_t)(mBase + row) * K + k0 + lc16 * 4);
        }
        #pragma unroll
        for (int i = 0; i < 4; ++i) {
            int row = lrow + i * 32;
            int nr = nBase + row; if (nr >= N) nr = N - 1;
            cp_async16(bb + row * ROWB + lc16 * 16,
                       BT + (size_t)nr * K + k0 + lc16 * 4);
        }
        asm volatile("cp.async.commit_group;" ::: "memory");
    };

    load_stage(0, 0);
    if (KT > 1) load_stage(1, 1);

    for (int kt = 0; kt < KT; ++kt) {
        const int s = kt % GSTG;
        asm volatile("cp.async.wait_group 1;" ::: "memory");
        __syncthreads();

        const char* As = sm + s * STG_BYTES + aOff;
        const char* Bs = sm + GSTG * STG_BYTES + s * STG_BYTES + bOff;

        #pragma unroll
        for (int ks = 0; ks < 4; ++ks) {
            const int kb = ks * 32;
            uint32_t af[2][4];
            #pragma unroll
            for (int t = 0; t < 2; ++t) {
                const char* a = As + t * (16 * ROWB) + kb;
                af[t][0] = *(const uint32_t*)(a);
                af[t][1] = *(const uint32_t*)(a + 8 * ROWB);
                af[t][2] = *(const uint32_t*)(a + 16);
                af[t][3] = *(const uint32_t*)(a + 8 * ROWB + 16);
            }
            uint32_t bf[8][2];
            #pragma unroll
            for (int j = 0; j < 8; ++j) {
                const char* bp = Bs + j * (8 * ROWB) + kb;
                bf[j][0] = *(const uint32_t*)(bp);
                bf[j][1] = *(const uint32_t*)(bp + 16);
            }
            #pragma unroll
            for (int t = 0; t < 2; ++t)
                #pragma unroll
                for (int j = 0; j < 8; ++j)
                    MMA_TF32(acc[t][j], af[t], bf[j]);
        }
        if (kt + 2 < KT) load_stage(kt + 2, (kt + 2) % GSTG);
    }

    #pragma unroll
    for (int t = 0; t < 2; ++t) {
        int r0 = mBase + wm * 32 + t * 16 + gid;
        #pragma unroll
        for (int j = 0; j < 8; ++j) {
            int c0 = nBase + wn * 64 + j * 8 + tig * 2;
            if (c0 + 1 < N) {
                *(float2*)&C[(size_t)r0 * N + c0]       = make_float2(acc[t][j][0], acc[t][j][1]);
                *(float2*)&C[(size_t)(r0 + 8) * N + c0] = make_float2(acc[t][j][2], acc[t][j][3]);
            } else if (c0 < N) {
                C[(size_t)r0 * N + c0]       = acc[t][j][0];
                C[(size_t)(r0 + 8) * N + c0] = acc[t][j][2];
            }
        }
    }
}

// ---------------- pre-rounding / weight transpose ----------------
__global__ __launch_bounds__(256) void round_u_kernel(const float* __restrict__ u, float* __restrict__ o)
{
    int idx = blockIdx.x * 256 + threadIdx.x;
    if (idx < ROWS * DMODEL / 4) {
        float4 v = ((const float4*)u)[idx];
        v.x = tf32r(v.x); v.y = tf32r(v.y); v.z = tf32r(v.z); v.w = tf32r(v.w);
        ((float4*)o)[idx] = v;
    }
}

__global__ __launch_bounds__(256) void transpose_round_kernel(
    const float* __restrict__ W, float* __restrict__ WT, int K, int N)
{
    __shared__ float tile[32][33];
    const int bx = blockIdx.x * 32, by = blockIdx.y * 32;
    const int x = threadIdx.x & 31, y = threadIdx.x >> 5;
    #pragma unroll
    for (int i = 0; i < 32; i += 8) {
        int k = by + y + i, n = bx + x;
        tile[y + i][x] = (k < K && n < N) ? W[(size_t)k * N + n] : 0.f;
    }
    __syncthreads();
    #pragma unroll
    for (int i = 0; i < 32; i += 8) {
        int n = bx + y + i, k = by + x;
        if (n < N && k < K) WT[(size_t)n * K + k] = tf32r(tile[x][y + i]);
    }
}

// ---------------- dt / A*dt (runs BEFORE conv so conv can fold dt into x) ----
__global__ __launch_bounds__(256) void dt_kernel(
    const float* __restrict__ dt_bias, const float* __restrict__ A_log)
{
    int idx = blockIdx.x * 256 + threadIdx.x;
    if (idx >= ROWS * NH) return;
    int r = idx >> 5;
    int h = idx & 31;
    float x = g_zxbcdt[(size_t)r * DPROJ + (DPROJ - NH) + h] + dt_bias[h];
    float sp = (x > 20.f) ? x : log1pf(expf(x));   // keep precise softplus
    g_dt[idx]  = sp;
    g_adt[idx] = -expf(A_log[h]) * sp;
}

// ---------------- conv + SiLU -> mma-ready layouts; x pre-scaled by dt -------
__global__ __launch_bounds__(256) void conv_silu_kernel(
    const float* __restrict__ conv_w, const float* __restrict__ conv_b)
{
    int idx = blockIdx.x * 256 + threadIdx.x;
    if (idx >= CONVD * (ROWS / 4)) return;
    const int ch = idx % CONVD;
    const int r4 = idx / CONVD;
    const int r0 = r4 * 4;
    const int b  = r0 >> 12;
    const int l0 = r0 & (LSEQ - 1);

    const float w0 = conv_w[ch * 4 + 0], w1 = conv_w[ch * 4 + 1];
    const float w2 = conv_w[ch * 4 + 2], w3 = conv_w[ch * 4 + 3];
    const float bias = conv_b[ch];

    float in[7];
    #pragma unroll
    for (int i = 0; i < 7; ++i) {
        int l = l0 - 3 + i;
        in[i] = (l >= 0) ? g_zxbcdt[(size_t)(r0 - 3 + i) * DPROJ + DIEXP + ch] : 0.f;
    }
    float o[4];
    #pragma unroll
    for (int k = 0; k < 4; ++k) {
        float a = bias;
        a = fmaf(in[k],     w0, a);
        a = fmaf(in[k + 1], w1, a);
        a = fmaf(in[k + 2], w2, a);
        a = fmaf(in[k + 3], w3, a);
        o[k] = a / (1.f + __expf(-a));
    }

    const int c  = l0 >> 6;
    const int s0 = l0 & 63;

    if (ch < DIEXP) {
        const int h = ch >> 6, p = ch & 63;
        #pragma unroll
        for (int k = 0; k < 4; ++k)
            o[k] *= g_dt[(r0 + k) * NH + h];
        const size_t base = (((size_t)((b * NC + c) * NH + h)) * HP + p) * CS + s0;
        *(float4*)&g_xt[base] = make_float4(o[0], o[1], o[2], o[3]);
    } else {
        const int cc = ch - DIEXP;   // 0..255
        #pragma unroll
        for (int k = 0; k < 4; ++k)
            g_bc[(size_t)(r0 + k) * 256 + cc] = tf32r(o[k]);
        if (cc < DS) {
            const size_t base = ((size_t)(b * NC + c) * DS + cc) * CS + s0;
            *(float4*)&g_bt[base] = make_float4(tf32r(o[0]), tf32r(o[1]), tf32r(o[2]), tf32r(o[3]));
        }
    }
}

// ---------------- per-(b,c,h) cumsum of adt ----------------
__global__ __launch_bounds__(256) void acum_kernel()
{
    int bch = blockIdx.x * 256 + threadIdx.x;
    if (bch >= NBCH) return;
    int h = bch & 31;
    int c = (bch >> 5) & 63;
    int b = bch >> 11;
    int rowBase = b * LSEQ + c * CS;
    float a = 0.f;
    #pragma unroll 8
    for (int s = 0; s < CS; ++s) {
        a += g_adt[(rowBase + s) * NH + h];
        g_acum[bch * CS + s] = a;
    }
    g_dchunk[bch] = __expf(a);
}

// ---------------- CB gram via mma ----------------
__global__ __launch_bounds__(256) void cb_kernel()
{
    extern __shared__ float dsm[];
    float* As = dsm;
    float* Bs = dsm + 64 * 132;
    const int bc = blockIdx.x;
    const int rowBase = bc * CS;
    const int tid = threadIdx.x;
    const int wid = tid >> 5, lane = tid & 31;
    const int gid = lane >> 2, tig = lane & 3;
    const int wm = wid >> 2, wn = wid & 3;

    for (int t = tid; t < 2048; t += 256) {
        int i = t >> 5, n4 = (t & 31) * 4;
        *(float4*)&As[i * 132 + n4] = *(const float4*)&g_bc[(size_t)(rowBase + i) * 256 + 128 + n4];
        *(float4*)&Bs[i * 132 + n4] = *(const float4*)&g_bc[(size_t)(rowBase + i) * 256 + n4];
    }
    __syncthreads();

    float acc[2][2][4];
    #pragma unroll
    for (int t = 0; t < 2; ++t)
        #pragma unroll
        for (int j = 0; j < 2; ++j)
            #pragma unroll
            for (int e = 0; e < 4; ++e) acc[t][j][e] = 0.f;

    const float* Aw = As + (wm * 32 + gid) * 132 + tig;
    const float* Bw = Bs + (wn * 16 + gid) * 132 + tig;
    #pragma unroll
    for (int ks = 0; ks < 16; ++ks) {
        const int ko = ks * 8;
        uint32_t af[2][4], bf[2][2];
        #pragma unroll
        for (int t = 0; t < 2; ++t) {
            const float* a = Aw + t * (16 * 132) + ko;
            af[t][0] = __float_as_uint(a[0]);
            af[t][1] = __float_as_uint(a[8 * 132]);
            af[t][2] = __float_as_uint(a[4]);
            af[t][3] = __float_as_uint(a[8 * 132 + 4]);
        }
        #pragma unroll
        for (int j = 0; j < 2; ++j) {
            const float* bp = Bw + j * (8 * 132) + ko;
            bf[j][0] = __float_as_uint(bp[0]);
            bf[j][1] = __float_as_uint(bp[4]);
        }
        #pragma unroll
        for (int t = 0; t < 2; ++t)
            #pragma unroll
            for (int j = 0; j < 2; ++j)
                MMA_TF32(acc[t][j], af[t], bf[j]);
    }

    #pragma unroll
    for (int t = 0; t < 2; ++t) {
        int i0 = wm * 32 + t * 16 + gid;
        #pragma unroll
        for (int j = 0; j < 2; ++j) {
            int j0 = wn * 16 + j * 8 + tig * 2;
            *(float2*)&g_CB[bc * 4096 + i0 * 64 + j0]       = make_float2(acc[t][j][0], acc[t][j][1]);
            *(float2*)&g_CB[bc * 4096 + (i0 + 8) * 64 + j0] = make_float2(acc[t][j][2], acc[t][j][3]);
        }
    }
}

// ---------------- states via mma (xt already includes dt) ----------------
__global__ __launch_bounds__(256) void states_kernel()
{
    extern __shared__ float dsm[];
    float* wv = dsm;
    float* As = dsm + 128;
    float* Bs = As + 64 * 68;
    const int c = blockIdx.x, b = blockIdx.y, h = blockIdx.z;
    const int bch = (b * NC + c) * NH + h;
    const int tid = threadIdx.x;
    const int wid = tid >> 5, lane = tid & 31;
    const int gid = lane >> 2, tig = lane & 3;
    const int wm = wid >> 2, wn = wid & 3;

    if (tid < CS) {
        float aend = g_acum[bch * CS + CS - 1];
        float ac   = g_acum[bch * CS + tid];
        wv[tid] = __expf(aend - ac);
    }
    __syncthreads();

    const float* xt = &g_xt[(size_t)bch * (HP * CS)];
    for (int t = tid; t < 1024; t += 256) {
        int p = t >> 4, s4 = (t & 15) * 4;
        float4 v = *(const float4*)&xt[p * CS + s4];
        v.x = tf32r(v.x * wv[s4 + 0]);
        v.y = tf32r(v.y * wv[s4 + 1]);
        v.z = tf32r(v.z * wv[s4 + 2]);
        v.w = tf32r(v.w * wv[s4 + 3]);
        *(float4*)&As[p * 68 + s4] = v;
    }
    const float* bt = &g_bt[(size_t)(b * NC + c) * (DS * CS)];
    for (int t = tid; t < 2048; t += 256) {
        int n = t >> 4, s4 = (t & 15) * 4;
        *(float4*)&Bs[n * 68 + s4] = *(const float4*)&bt[n * CS + s4];
    }
    __syncthreads();

    float acc[2][4][4];
    #pragma unroll
    for (int t = 0; t < 2; ++t)
        #pragma unroll
        for (int j = 0; j < 4; ++j)
            #pragma unroll
            for (int e = 0; e < 4; ++e) acc[t][j][e] = 0.f;

    const float* Aw = As + (wm * 32 + gid) * 68 + tig;
    const float* Bw = Bs + (wn * 32 + gid) * 68 + tig;
    #pragma unroll
    for (int ks = 0; ks < 8; ++ks) {
        const int ko = ks * 8;
        uint32_t af[2][4], bf[4][2];
        #pragma unroll
        for (int t = 0; t < 2; ++t) {
            const float* a = Aw + t * (16 * 68) + ko;
            af[t][0] = __float_as_uint(a[0]);
            af[t][1] = __float_as_uint(a[8 * 68]);
            af[t][2] = __float_as_uint(a[4]);
            af[t][3] = __float_as_uint(a[8 * 68 + 4]);
        }
        #pragma unroll
        for (int j = 0; j < 4; ++j) {
            const float* bp = Bw + j * (8 * 68) + ko;
            bf[j][0] = __float_as_uint(bp[0]);
            bf[j][1] = __float_as_uint(bp[4]);
        }
        #pragma unroll
        for (int t = 0; t < 2; ++t)
            #pragma unroll
            for (int j = 0; j < 4; ++j)
                MMA_TF32(acc[t][j], af[t], bf[j]);
    }

    float* S = &g_states[(size_t)bch * (HP * DS)];
    #pragma unroll
    for (int t = 0; t < 2; ++t) {
        int p0 = wm * 32 + t * 16 + gid;
        #pragma unroll
        for (int j = 0; j < 4; ++j) {
            int n0 = wn * 32 + j * 8 + tig * 2;
            *(float2*)&S[p0 * DS + n0]       = make_float2(acc[t][j][0], acc[t][j][1]);
            *(float2*)&S[(p0 + 8) * DS + n0] = make_float2(acc[t][j][2], acc[t][j][3]);
        }
    }
}

// ---------------- inter-chunk recurrence (float4, plain fp32 writes) ---------
__global__ __launch_bounds__(256) void recur_kernel()
{
    const int bid = blockIdx.x;          // 0 .. BSZ*NH*8-1
    const int bh  = bid >> 3;            // b*NH + h
    const int eo4 = ((bid & 7) << 8) + threadIdx.x;   // float4 index 0..2047
    const int b = bh >> 5, h = bh & 31;

    float4 S = make_float4(0.f, 0.f, 0.f, 0.f);
    for (int c = 0; c < NC; ++c) {
        int bch = (b * NC + c) * NH + h;
        float d = g_dchunk[bch];
        float4* ptr = (float4*)&g_states[(size_t)bch * (HP * DS)] + eo4;
        float4 t = *ptr;
        *ptr = S;
        S.x = fmaf(d, S.x, t.x);
        S.y = fmaf(d, S.y, t.y);
        S.z = fmaf(d, S.z, t.z);
        S.w = fmaf(d, S.w, t.w);
    }
}

// ---------------- Y via mma: Yoff (K=128) + Yd (K=64); xt includes dt --------
__global__ __launch_bounds__(256) void y_kernel()
{
    extern __shared__ float dsm[];
    float* avec = dsm;
    float* eac  = dsm + 64;
    float* As   = dsm + 256;
    float* Bs   = As + 64 * 132;
    const int c = blockIdx.x, b = blockIdx.y, h = blockIdx.z;
    const int bch = (b * NC + c) * NH + h;
    const int rowBase = b * LSEQ + c * CS;
    const int tid = threadIdx.x;
    const int wid = tid >> 5, lane = tid & 31;
    const int gid = lane >> 2, tig = lane & 3;
    const int wm = wid >> 2, wn = wid & 3;

    if (tid < CS) {
        float ac = g_acum[bch * CS + tid];
        avec[tid] = ac;
        eac[tid]  = __expf(ac);
    }
    __syncthreads();

    const float* Sin = &g_states[(size_t)bch * (HP * DS)];
    for (int t = tid; t < 2048; t += 256) {
        int i = t >> 5, n4 = (t & 31) * 4;
        float e = eac[i];
        float4 cv = *(const float4*)&g_bc[(size_t)(rowBase + i) * 256 + 128 + n4];
        cv.x = tf32r(cv.x * e); cv.y = tf32r(cv.y * e);
        cv.z = tf32r(cv.z * e); cv.w = tf32r(cv.w * e);
        *(float4*)&As[i * 132 + n4] = cv;
        float4 sv = *(const float4*)&Sin[i * DS + n4];
        sv.x = tf32r(sv.x); sv.y = tf32r(sv.y);
        sv.z = tf32r(sv.z); sv.w = tf32r(sv.w);
        *(float4*)&Bs[i * 132 + n4] = sv;
    }
    __syncthreads();

    float acc[2][2][4];
    #pragma unroll
    for (int t = 0; t < 2; ++t)
        #pragma unroll
        for (int j = 0; j < 2; ++j)
            #pragma unroll
            for (int e = 0; e < 4; ++e) acc[t][j][e] = 0.f;

    {
        const float* Aw = As + (wm * 32 + gid) * 132 + tig;
        const float* Bw = Bs + (wn * 16 + gid) * 132 + tig;
        #pragma unroll
        for (int ks = 0; ks < 16; ++ks) {
            const int ko = ks * 8;
            uint32_t af[2][4], bf[2][2];
            #pragma unroll
            for (int t = 0; t < 2; ++t) {
                const float* a = Aw + t * (16 * 132) + ko;
                af[t][0] = __float_as_uint(a[0]);
                af[t][1] = __float_as_uint(a[8 * 132]);
                af[t][2] = __float_as_uint(a[4]);
                af[t][3] = __float_as_uint(a[8 * 132 + 4]);
            }
            #pragma unroll
            for (int j = 0; j < 2; ++j) {
                const float* bp = Bw + j * (8 * 132) + ko;
                bf[j][0] = __float_as_uint(bp[0]);
                bf[j][1] = __float_as_uint(bp[4]);
            }
            #pragma unroll
            for (int t = 0; t < 2; ++t)
                #pragma unroll
                for (int j = 0; j < 2; ++j)
                    MMA_TF32(acc[t][j], af[t], bf[j]);
        }
    }
    __syncthreads();

    const int cbBase = (b * NC + c) * 4096;
    for (int t = tid; t < 4096; t += 256) {
        int i = t >> 6, jj = t & 63;
        float w = 0.f;
        if (jj <= i) w = tf32r(g_CB[cbBase + i * 64 + jj] * __expf(avec[i] - avec[jj]));
        As[i * 68 + jj] = w;
    }
    const float* xt = &g_xt[(size_t)bch * (HP * CS)];
    for (int t = tid; t < 1024; t += 256) {
        int p = t >> 4, j4 = (t & 15) * 4;
        float4 v = *(const float4*)&xt[p * CS + j4];
        v.x = tf32r(v.x); v.y = tf32r(v.y);
        v.z = tf32r(v.z); v.w = tf32r(v.w);
        *(float4*)&Bs[p * 68 + j4] = v;
    }
    __syncthreads();

    {
        const float* Aw = As + (wm * 32 + gid) * 68 + tig;
        const float* Bw = Bs + (wn * 16 + gid) * 68 + tig;
        #pragma unroll
        for (int ks = 0; ks < 8; ++ks) {
            const int ko = ks * 8;
            uint32_t af[2][4], bf[2][2];
            #pragma unroll
            for (int t = 0; t < 2; ++t) {
                const float* a = Aw + t * (16 * 68) + ko;
                af[t][0] = __float_as_uint(a[0]);
                af[t][1] = __float_as_uint(a[8 * 68]);
                af[t][2] = __float_as_uint(a[4]);
                af[t][3] = __float_as_uint(a[8 * 68 + 4]);
            }
            #pragma unroll
            for (int j = 0; j < 2; ++j) {
                const float* bp = Bw + j * (8 * 68) + ko;
                bf[j][0] = __float_as_uint(bp[0]);
                bf[j][1] = __float_as_uint(bp[4]);
            }
            #pragma unroll
            for (int t = 0; t < 2; ++t)
                #pragma unroll
                for (int j = 0; j < 2; ++j)
                    MMA_TF32(acc[t][j], af[t], bf[j]);
        }
    }

    #pragma unroll
    for (int t = 0; t < 2; ++t) {
        int i0 = wm * 32 + t * 16 + gid;
        #pragma unroll
        for (int j = 0; j < 2; ++j) {
            int col = h * HP + wn * 16 + j * 8 + tig * 2;
            *(float2*)&g_y[(size_t)(rowBase + i0) * DIEXP + col]
                = make_float2(acc[t][j][0], acc[t][j][1]);
            *(float2*)&g_y[(size_t)(rowBase + i0 + 8) * DIEXP + col]
                = make_float2(acc[t][j][2], acc[t][j][3]);
        }
    }
}

// ---------------- gate + LayerNorm (float4 IO, warp-shuffle reductions) ------
__global__ __launch_bounds__(256) void gatenorm_kernel(
    const float* __restrict__ norm_w, const float* __restrict__ norm_b)
{
    const int r = blockIdx.x;
    const int tid = threadIdx.x;
    const int wid = tid >> 5, lane = tid & 31;
    __shared__ float ws1[8];
    __shared__ float ws2[8];

    float v[8];
    float lsum = 0.f;
    #pragma unroll
    for (int g = 0; g < 2; ++g) {
        int col = g * 1024 + tid * 4;
        float4 vz = *(const float4*)&g_zxbcdt[(size_t)r * DPROJ + col];
        float4 vy = *(const float4*)&g_y[(size_t)r * DIEXP + col];
        const float* zp = (const float*)&vz;
        const float* yp = (const float*)&vy;
        #pragma unroll
        for (int e = 0; e < 4; ++e) {
            float z = zp[e];
            float val = yp[e] * (z / (1.f + __expf(-z)));
            v[g * 4 + e] = val;
            lsum += val;
        }
    }
    #pragma unroll
    for (int o = 16; o > 0; o >>= 1) lsum += __shfl_xor_sync(0xffffffffu, lsum, o);
    if (lane == 0) ws1[wid] = lsum;
    __syncthreads();
    float tot = 0.f;
    #pragma unroll
    for (int i = 0; i < 8; ++i) tot += ws1[i];
    const float mu = tot / (float)DIEXP;

    float ls2 = 0.f;
    #pragma unroll
    for (int e = 0; e < 8; ++e) { float d = v[e] - mu; ls2 = fmaf(d, d, ls2); }
    #pragma unroll
    for (int o = 16; o > 0; o >>= 1) ls2 += __shfl_xor_sync(0xffffffffu, ls2, o);
    if (lane == 0) ws2[wid] = ls2;
    __syncthreads();
    float tot2 = 0.f;
    #pragma unroll
    for (int i = 0; i < 8; ++i) tot2 += ws2[i];
    const float rstd = rsqrtf(tot2 / (float)DIEXP + 1e-5f);

    #pragma unroll
    for (int g = 0; g < 2; ++g) {
        int col = g * 1024 + tid * 4;
        float4 w  = *(const float4*)&norm_w[col];
        float4 bb = *(const float4*)&norm_b[col];
        float4 o4;
        o4.x = tf32r((v[g * 4 + 0] - mu) * rstd * w.x + bb.x);
        o4.y = tf32r((v[g * 4 + 1] - mu) * rstd * w.y + bb.y);
        o4.z = tf32r((v[g * 4 + 2] - mu) * rstd * w.z + bb.z);
        o4.w = tf32r((v[g * 4 + 3] - mu) * rstd * w.w + bb.w);
        *(float4*)&g_y[(size_t)r * DIEXP + col] = o4;
    }
}

// ---------------- launch ----------------
extern "C" void kernel_launch(void* const* d_in, const int* in_sizes, int n_in,
                              void* d_out, int out_size)
{
    const float* u       = (const float*)d_in[0];
    const float* W_in    = (const float*)d_in[1];
    const float* conv_w  = (const float*)d_in[2];
    const float* conv_b  = (const float*)d_in[3];
    const float* dt_bias = (const float*)d_in[4];
    const float* A_log   = (const float*)d_in[5];
    const float* norm_w  = (const float*)d_in[6];
    const float* norm_b  = (const float*)d_in[7];
    const float* W_out   = (const float*)d_in[8];
    float* out = (float*)d_out;

    float *zx = nullptr, *yb = nullptr, *sc = nullptr, *wt = nullptr;
    cudaGetSymbolAddress((void**)&zx, g_zxbcdt);
    cudaGetSymbolAddress((void**)&yb, g_y);
    cudaGetSymbolAddress((void**)&sc, g_states);
    cudaGetSymbolAddress((void**)&wt, g_WT);

    const int GEMM_SMEM   = 2 * GSTG * STG_BYTES;                  // 110592
    const int CB_SMEM     = 2 * 64 * 132 * 4;
    const int STATES_SMEM = (128 + 64 * 68 + 128 * 68) * 4;
    const int Y_SMEM      = (256 + 2 * 64 * 132) * 4;
    cudaFuncSetAttribute(gemm_mma_kernel, cudaFuncAttributeMaxDynamicSharedMemorySize, GEMM_SMEM);
    cudaFuncSetAttribute(cb_kernel,       cudaFuncAttributeMaxDynamicSharedMemorySize, CB_SMEM);
    cudaFuncSetAttribute(states_kernel,   cudaFuncAttributeMaxDynamicSharedMemorySize, STATES_SMEM);
    cudaFuncSetAttribute(y_kernel,        cudaFuncAttributeMaxDynamicSharedMemorySize, Y_SMEM);

    // 0) pre-round u; transpose+round weights
    round_u_kernel<<<(ROWS * DMODEL / 4 + 255) / 256, 256>>>(u, sc);
    transpose_round_kernel<<<dim3((DPROJ + 31) / 32, (DMODEL + 31) / 32), 256>>>(
        W_in, wt, DMODEL, DPROJ);
    transpose_round_kernel<<<dim3((DMODEL + 31) / 32, (DIEXP + 31) / 32), 256>>>(
        W_out, wt + (size_t)DPROJ * DMODEL, DIEXP, DMODEL);

    // 1) zxbcdt = u @ W_in
    gemm_mma_kernel<<<dim3((DPROJ + 127) / 128, ROWS / 128), 256, GEMM_SMEM>>>(
        sc, wt, zx, ROWS, DPROJ, DMODEL);
    // 2) dt first (conv folds dt into x), then conv, then cumsums
    dt_kernel<<<(ROWS * NH + 255) / 256, 256>>>(dt_bias, A_log);
    conv_silu_kernel<<<(CONVD * (ROWS / 4) + 255) / 256, 256>>>(conv_w, conv_b);
    acum_kernel<<<(NBCH + 255) / 256, 256>>>();
    // 4) CB gram (mma)
    cb_kernel<<<BSZ * NC, 256, CB_SMEM>>>();
    // 5) per-chunk states (mma)
    states_kernel<<<dim3(NC, BSZ, NH), 256, STATES_SMEM>>>();
    // 6) inter-chunk recurrence (float4)
    recur_kernel<<<BSZ * NH * 8, 256>>>();
    // 7) Y (mma)
    y_kernel<<<dim3(NC, BSZ, NH), 256, Y_SMEM>>>();
    // 8) gate + layernorm (float4 IO, warp-shuffle)
    gatenorm_kernel<<<ROWS, 256>>>(norm_w, norm_b);
    // 9) out = y @ W_out
    gemm_mma_kernel<<<dim3(DMODEL / 128, ROWS / 128), 256, GEMM_SMEM>>>(
        yb, wt + (size_t)DPROJ * DMODEL, out, ROWS, DMODEL, DIEXP);
}